// round 6
// baseline (speedup 1.0000x reference)
#include <cuda_runtime.h>
#include <cstdint>

// Problem shape
#define BDIM   8192
#define DDIM   2048
#define NUNITS 2048
#define KW     64          // 2048 bits = 64 u32 words per row

// Packed sign bits, tiled: tile t holds 128 rows, layout [tile][j][rowInTile]
__device__ __align__(128) uint32_t g_Abits[(size_t)(BDIM / 128) * KW * 128];   // 2 MB
__device__ __align__(128) uint32_t g_Bbits[(size_t)(NUNITS / 128) * KW * 128]; // 512 KB

// ============================ Pack kernels ============================

// 8 words per warp, loads hoisted for MLP
__global__ void pack_a_kernel(const float* __restrict__ in, uint32_t* __restrict__ bits) {
    int lane = threadIdx.x & 31;
    int warp = (blockIdx.x * blockDim.x + threadIdx.x) >> 5;
    float v[8];
#pragma unroll
    for (int s = 0; s < 8; s++) {
        int w = warp * 8 + s;
        int m = w >> 6, j = w & 63;
        v[s] = in[(size_t)m * DDIM + j * 32 + lane];
    }
#pragma unroll
    for (int s = 0; s < 8; s++) {
        int w = warp * 8 + s;
        int m = w >> 6, j = w & 63;
        uint32_t word = __ballot_sync(0xFFFFFFFFu, v[s] < 0.0f);
        if (lane == 0)
            bits[(size_t)(m >> 7) * (KW * 128) + j * 128 + (m & 127)] = word;
    }
}

__global__ void pack_b_kernel(const float* __restrict__ kern, uint32_t* __restrict__ bits) {
    __shared__ uint8_t tile[32][33];          // [k][n]
    int n0 = blockIdx.x * 32;
    int k0 = blockIdx.y * 32;
    int tx = threadIdx.x, ty = threadIdx.y;   // (32, 8)
#pragma unroll
    for (int s = 0; s < 4; s++) {
        int kk = ty + s * 8;
        float v = kern[(size_t)(k0 + kk) * NUNITS + n0 + tx];
        tile[kk][tx] = (v < 0.0f) ? 1 : 0;
    }
    __syncthreads();
    int wid = (ty * 32 + tx) >> 5;
    int lane = tx;
#pragma unroll
    for (int s = 0; s < 4; s++) {
        int nl = wid * 4 + s;
        uint32_t word = __ballot_sync(0xFFFFFFFFu, tile[lane][nl] != 0);
        if (lane == 0) {
            int n = n0 + nl;
            bits[(size_t)(n >> 7) * (KW * 128) + blockIdx.y * 128 + (n & 127)] = word;
        }
    }
}

// ============================ popcount GEMM (mixed CSA, pipe-balanced) ====
// out[m][n] = 2048 - 2 * sum_j popc(A[m][j] ^ B[n][j]) + bias[n]
// Words 0..47: 16 CSA triples (2 POPC per 3 words). Words 48..63: raw.
// One raw word folded into each triple iteration -> local alu/popc mix.
// Accumulation forced onto fma pipe via IMAD with opaque multipliers.

__global__ void __launch_bounds__(256) popc_gemm(
    const uint32_t* __restrict__ Ab, const uint32_t* __restrict__ Bb,
    const float* __restrict__ bias, float* __restrict__ out)
{
    extern __shared__ uint32_t smem[];        // A tile 8192 words, B tile 8192 words, +2
    uint32_t* Asm = smem;
    uint32_t* Bsm = smem + KW * 128;
    int* mult = (int*)(smem + 2 * KW * 128);

    const int tid = threadIdx.x;
    const int nblk = blockIdx.x, mblk = blockIdx.y;

    if (tid == 0) { mult[0] = 1; mult[1] = 2; }   // opaque to ptxas -> keeps IMAD on fma

    // one-shot cooperative copy: 2048 uint4 per tile, 8 per thread
    {
        const uint4* gA = (const uint4*)(Ab + (size_t)mblk * (KW * 128));
        const uint4* gB = (const uint4*)(Bb + (size_t)nblk * (KW * 128));
        uint4* sA = (uint4*)Asm;
        uint4* sB = (uint4*)Bsm;
#pragma unroll
        for (int i = 0; i < 8; i++) {
            sA[tid + i * 256] = gA[tid + i * 256];
            sB[tid + i * 256] = gB[tid + i * 256];
        }
    }
    __syncthreads();

    const int k1 = mult[0];                   // == 1, unknown to compiler
    const int k2 = mult[1];                   // == 2, unknown to compiler

    const int tx = tid & 15;                  // n sub-block
    const int ty = tid >> 4;                  // m sub-block

    int acc[8][8];
#pragma unroll
    for (int i = 0; i < 8; i++)
#pragma unroll
        for (int k = 0; k < 8; k++) acc[i][k] = 0;

#pragma unroll 2
    for (int jg = 0; jg < 16; jg++) {
        // CSA triple: words 3jg, 3jg+1, 3jg+2 ; raw word: 48+jg
        uint32_t a0[8], a1[8], a2[8], ar[8], b0[8], b1[8], b2[8], br[8];
        const uint32_t* Ap = &Asm[(jg * 3) * 128 + ty * 8];
        const uint32_t* Bp = &Bsm[(jg * 3) * 128 + tx * 8];
        const uint32_t* Aq = &Asm[(48 + jg) * 128 + ty * 8];
        const uint32_t* Bq = &Bsm[(48 + jg) * 128 + tx * 8];
        *(uint4*)&a0[0] = *(const uint4*)&Ap[0];   *(uint4*)&a0[4] = *(const uint4*)&Ap[4];
        *(uint4*)&a1[0] = *(const uint4*)&Ap[128]; *(uint4*)&a1[4] = *(const uint4*)&Ap[132];
        *(uint4*)&a2[0] = *(const uint4*)&Ap[256]; *(uint4*)&a2[4] = *(const uint4*)&Ap[260];
        *(uint4*)&ar[0] = *(const uint4*)&Aq[0];   *(uint4*)&ar[4] = *(const uint4*)&Aq[4];
        *(uint4*)&b0[0] = *(const uint4*)&Bp[0];   *(uint4*)&b0[4] = *(const uint4*)&Bp[4];
        *(uint4*)&b1[0] = *(const uint4*)&Bp[128]; *(uint4*)&b1[4] = *(const uint4*)&Bp[132];
        *(uint4*)&b2[0] = *(const uint4*)&Bp[256]; *(uint4*)&b2[4] = *(const uint4*)&Bp[260];
        *(uint4*)&br[0] = *(const uint4*)&Bq[0];   *(uint4*)&br[4] = *(const uint4*)&Bq[4];
#pragma unroll
        for (int mi = 0; mi < 8; mi++) {
#pragma unroll
            for (int ni = 0; ni < 8; ni++) {
                uint32_t x0 = a0[mi] ^ b0[ni];
                uint32_t x1 = a1[mi] ^ b1[ni];
                uint32_t x2 = a2[mi] ^ b2[ni];
                uint32_t xr = ar[mi] ^ br[ni];
                uint32_t s = x0 ^ x1 ^ x2;                      // LOP3 0x96
                uint32_t c = (x0 & x1) | (x2 & (x0 | x1));      // LOP3 0xE8 (majority)
                int a = acc[mi][ni];
                a = k1 * __popc(xr) + a;                        // IMAD (fma pipe)
                a = k2 * __popc(c)  + a;                        // IMAD
                a = k1 * __popc(s)  + a;                        // IMAD
                acc[mi][ni] = a;
            }
        }
    }

    // epilogue: val = 2048 - 2*acc + bias
    const int n0 = nblk * 128 + tx * 8;
    float bl[8];
    *(float4*)&bl[0] = *(const float4*)&bias[n0];
    *(float4*)&bl[4] = *(const float4*)&bias[n0 + 4];
#pragma unroll
    for (int i = 0; i < 8; i++) bl[i] += 2048.0f;

#pragma unroll
    for (int mi = 0; mi < 8; mi++) {
        size_t row = (size_t)(mblk * 128 + ty * 8 + mi) * NUNITS + n0;
        float4 v0, v1;
        v0.x = fmaf(-2.0f, (float)acc[mi][0], bl[0]);
        v0.y = fmaf(-2.0f, (float)acc[mi][1], bl[1]);
        v0.z = fmaf(-2.0f, (float)acc[mi][2], bl[2]);
        v0.w = fmaf(-2.0f, (float)acc[mi][3], bl[3]);
        v1.x = fmaf(-2.0f, (float)acc[mi][4], bl[4]);
        v1.y = fmaf(-2.0f, (float)acc[mi][5], bl[5]);
        v1.z = fmaf(-2.0f, (float)acc[mi][6], bl[6]);
        v1.w = fmaf(-2.0f, (float)acc[mi][7], bl[7]);
        *(float4*)&out[row]     = v0;
        *(float4*)&out[row + 4] = v1;
    }
}

// ============================ Host ============================

#define GEMM_SMEM (2 * KW * 128 * 4 + 16)   // 64 KB + mult words

extern "C" void kernel_launch(void* const* d_in, const int* in_sizes, int n_in,
                              void* d_out, int out_size) {
    const float* inputs = (const float*)d_in[0];
    const float* kern   = (const float*)d_in[1];
    const float* bias   = (const float*)d_in[2];
    float* out = (float*)d_out;

    void* pA = nullptr; void* pB = nullptr;
    cudaGetSymbolAddress(&pA, g_Abits);
    cudaGetSymbolAddress(&pB, g_Bbits);

    // 1) pack A: 8 words per warp, 8 warps per block
    {
        int words = BDIM * KW;
        int blocks = words / (8 * 8);          // 8192
        pack_a_kernel<<<blocks, 256>>>(inputs, (uint32_t*)pA);
    }
    // 2) pack + transpose B
    {
        dim3 tb(32, 8), tg(NUNITS / 32, DDIM / 32);
        pack_b_kernel<<<tg, tb>>>(kern, (uint32_t*)pB);
    }
    // 3) mixed-CSA popcount GEMM
    cudaFuncSetAttribute(popc_gemm, cudaFuncAttributeMaxDynamicSharedMemorySize, GEMM_SMEM);
    dim3 grid(NUNITS / 128, BDIM / 128);       // (16, 64)
    popc_gemm<<<grid, 256, GEMM_SMEM>>>((const uint32_t*)pA, (const uint32_t*)pB, bias, out);
}

// round 7
// speedup vs baseline: 1.0339x; 1.0339x over previous
#include <cuda_runtime.h>
#include <cstdint>

// Problem shape
#define BDIM   8192
#define DDIM   2048
#define NUNITS 2048
#define KW     64          // 2048 bits = 64 u32 words per row

// Packed sign bits, tiled: tile t holds 128 rows, layout [tile][j][rowInTile]
__device__ __align__(128) uint32_t g_Abits[(size_t)(BDIM / 128) * KW * 128];   // 2 MB
__device__ __align__(128) uint32_t g_Bbits[(size_t)(NUNITS / 128) * KW * 128]; // 512 KB

// ============================ Pack kernels ============================

// 8 words per warp, loads hoisted for MLP
__global__ void pack_a_kernel(const float* __restrict__ in, uint32_t* __restrict__ bits) {
    int lane = threadIdx.x & 31;
    int warp = (blockIdx.x * blockDim.x + threadIdx.x) >> 5;
    float v[8];
#pragma unroll
    for (int s = 0; s < 8; s++) {
        int w = warp * 8 + s;
        int m = w >> 6, j = w & 63;
        v[s] = in[(size_t)m * DDIM + j * 32 + lane];
    }
#pragma unroll
    for (int s = 0; s < 8; s++) {
        int w = warp * 8 + s;
        int m = w >> 6, j = w & 63;
        uint32_t word = __ballot_sync(0xFFFFFFFFu, v[s] < 0.0f);
        if (lane == 0)
            bits[(size_t)(m >> 7) * (KW * 128) + j * 128 + (m & 127)] = word;
    }
}

__global__ void pack_b_kernel(const float* __restrict__ kern, uint32_t* __restrict__ bits) {
    __shared__ uint8_t tile[32][33];          // [k][n]
    int n0 = blockIdx.x * 32;
    int k0 = blockIdx.y * 32;
    int tx = threadIdx.x, ty = threadIdx.y;   // (32, 8)
#pragma unroll
    for (int s = 0; s < 4; s++) {
        int kk = ty + s * 8;
        float v = kern[(size_t)(k0 + kk) * NUNITS + n0 + tx];
        tile[kk][tx] = (v < 0.0f) ? 1 : 0;
    }
    __syncthreads();
    int wid = (ty * 32 + tx) >> 5;
    int lane = tx;
#pragma unroll
    for (int s = 0; s < 4; s++) {
        int nl = wid * 4 + s;
        uint32_t word = __ballot_sync(0xFFFFFFFFu, tile[lane][nl] != 0);
        if (lane == 0) {
            int n = n0 + nl;
            bits[(size_t)(n >> 7) * (KW * 128) + blockIdx.y * 128 + (n & 127)] = word;
        }
    }
}

// ============================ popcount GEMM (3:2 CSA, 2 CTAs/SM) =========
// out[m][n] = 2048 - 2 * sum_j popc(A[m][j] ^ B[n][j]) + bias[n]
// Words 0..59: 20 CSA triples. Words 60..63: raw, IADD3-batched.

__global__ void __launch_bounds__(256, 2) popc_gemm(
    const uint32_t* __restrict__ Ab, const uint32_t* __restrict__ Bb,
    const float* __restrict__ bias, float* __restrict__ out)
{
    extern __shared__ uint32_t smem[];        // A tile 8192 words, B tile 8192 words
    uint32_t* Asm = smem;
    uint32_t* Bsm = smem + KW * 128;

    const int tid = threadIdx.x;
    const int nblk = blockIdx.x, mblk = blockIdx.y;

    // one-shot cooperative copy: 2048 uint4 per tile, 8 per thread
    {
        const uint4* gA = (const uint4*)(Ab + (size_t)mblk * (KW * 128));
        const uint4* gB = (const uint4*)(Bb + (size_t)nblk * (KW * 128));
        uint4* sA = (uint4*)Asm;
        uint4* sB = (uint4*)Bsm;
#pragma unroll
        for (int i = 0; i < 8; i++) {
            sA[tid + i * 256] = gA[tid + i * 256];
            sB[tid + i * 256] = gB[tid + i * 256];
        }
    }
    __syncthreads();

    const int tx = tid & 15;                  // n sub-block
    const int ty = tid >> 4;                  // m sub-block

    int acc[8][8];
#pragma unroll
    for (int i = 0; i < 8; i++)
#pragma unroll
        for (int k = 0; k < 8; k++) acc[i][k] = 0;

    // 20 CSA triples (words 0..59)
#pragma unroll 2
    for (int jg = 0; jg < 20; jg++) {
        uint32_t a0[8], a1[8], a2[8], b0[8], b1[8], b2[8];
        const uint32_t* Ap = &Asm[(jg * 3) * 128 + ty * 8];
        const uint32_t* Bp = &Bsm[(jg * 3) * 128 + tx * 8];
        *(uint4*)&a0[0] = *(const uint4*)&Ap[0];   *(uint4*)&a0[4] = *(const uint4*)&Ap[4];
        *(uint4*)&a1[0] = *(const uint4*)&Ap[128]; *(uint4*)&a1[4] = *(const uint4*)&Ap[132];
        *(uint4*)&a2[0] = *(const uint4*)&Ap[256]; *(uint4*)&a2[4] = *(const uint4*)&Ap[260];
        *(uint4*)&b0[0] = *(const uint4*)&Bp[0];   *(uint4*)&b0[4] = *(const uint4*)&Bp[4];
        *(uint4*)&b1[0] = *(const uint4*)&Bp[128]; *(uint4*)&b1[4] = *(const uint4*)&Bp[132];
        *(uint4*)&b2[0] = *(const uint4*)&Bp[256]; *(uint4*)&b2[4] = *(const uint4*)&Bp[260];
#pragma unroll
        for (int mi = 0; mi < 8; mi++) {
#pragma unroll
            for (int ni = 0; ni < 8; ni++) {
                uint32_t x0 = a0[mi] ^ b0[ni];
                uint32_t x1 = a1[mi] ^ b1[ni];
                uint32_t x2 = a2[mi] ^ b2[ni];
                uint32_t s = x0 ^ x1 ^ x2;                      // LOP3 0x96
                uint32_t c = (x0 & x1) | (x2 & (x0 | x1));      // LOP3 0xE8 (majority)
                acc[mi][ni] += __popc(s) + 2 * __popc(c);
            }
        }
    }
    // raw tail: words 60..63, popcs batched via 3-input adds
    {
        uint32_t a0[8], a1[8], a2[8], a3[8], b0[8], b1[8], b2[8], b3[8];
        const uint32_t* Ap = &Asm[60 * 128 + ty * 8];
        const uint32_t* Bp = &Bsm[60 * 128 + tx * 8];
        *(uint4*)&a0[0] = *(const uint4*)&Ap[0];   *(uint4*)&a0[4] = *(const uint4*)&Ap[4];
        *(uint4*)&a1[0] = *(const uint4*)&Ap[128]; *(uint4*)&a1[4] = *(const uint4*)&Ap[132];
        *(uint4*)&a2[0] = *(const uint4*)&Ap[256]; *(uint4*)&a2[4] = *(const uint4*)&Ap[260];
        *(uint4*)&a3[0] = *(const uint4*)&Ap[384]; *(uint4*)&a3[4] = *(const uint4*)&Ap[388];
        *(uint4*)&b0[0] = *(const uint4*)&Bp[0];   *(uint4*)&b0[4] = *(const uint4*)&Bp[4];
        *(uint4*)&b1[0] = *(const uint4*)&Bp[128]; *(uint4*)&b1[4] = *(const uint4*)&Bp[132];
        *(uint4*)&b2[0] = *(const uint4*)&Bp[256]; *(uint4*)&b2[4] = *(const uint4*)&Bp[260];
        *(uint4*)&b3[0] = *(const uint4*)&Bp[384]; *(uint4*)&b3[4] = *(const uint4*)&Bp[388];
#pragma unroll
        for (int mi = 0; mi < 8; mi++) {
#pragma unroll
            for (int ni = 0; ni < 8; ni++) {
                int p0 = __popc(a0[mi] ^ b0[ni]);
                int p1 = __popc(a1[mi] ^ b1[ni]);
                int p2 = __popc(a2[mi] ^ b2[ni]);
                int p3 = __popc(a3[mi] ^ b3[ni]);
                acc[mi][ni] += (p0 + p1) + (p2 + p3);
            }
        }
    }

    // epilogue: val = 2048 - 2*acc + bias
    const int n0 = nblk * 128 + tx * 8;
    float bl[8];
    *(float4*)&bl[0] = *(const float4*)&bias[n0];
    *(float4*)&bl[4] = *(const float4*)&bias[n0 + 4];
#pragma unroll
    for (int i = 0; i < 8; i++) bl[i] += 2048.0f;

#pragma unroll
    for (int mi = 0; mi < 8; mi++) {
        size_t row = (size_t)(mblk * 128 + ty * 8 + mi) * NUNITS + n0;
        float4 v0, v1;
        v0.x = fmaf(-2.0f, (float)acc[mi][0], bl[0]);
        v0.y = fmaf(-2.0f, (float)acc[mi][1], bl[1]);
        v0.z = fmaf(-2.0f, (float)acc[mi][2], bl[2]);
        v0.w = fmaf(-2.0f, (float)acc[mi][3], bl[3]);
        v1.x = fmaf(-2.0f, (float)acc[mi][4], bl[4]);
        v1.y = fmaf(-2.0f, (float)acc[mi][5], bl[5]);
        v1.z = fmaf(-2.0f, (float)acc[mi][6], bl[6]);
        v1.w = fmaf(-2.0f, (float)acc[mi][7], bl[7]);
        *(float4*)&out[row]     = v0;
        *(float4*)&out[row + 4] = v1;
    }
}

// ============================ Host ============================

#define GEMM_SMEM (2 * KW * 128 * 4)   // 64 KB -> 2 CTAs/SM fits 128 KB < 228 KB

extern "C" void kernel_launch(void* const* d_in, const int* in_sizes, int n_in,
                              void* d_out, int out_size) {
    const float* inputs = (const float*)d_in[0];
    const float* kern   = (const float*)d_in[1];
    const float* bias   = (const float*)d_in[2];
    float* out = (float*)d_out;

    void* pA = nullptr; void* pB = nullptr;
    cudaGetSymbolAddress(&pA, g_Abits);
    cudaGetSymbolAddress(&pB, g_Bbits);

    // 1) pack A: 8 words per warp, 8 warps per block
    {
        int words = BDIM * KW;
        int blocks = words / (8 * 8);          // 8192
        pack_a_kernel<<<blocks, 256>>>(inputs, (uint32_t*)pA);
    }
    // 2) pack + transpose B
    {
        dim3 tb(32, 8), tg(NUNITS / 32, DDIM / 32);
        pack_b_kernel<<<tg, tb>>>(kern, (uint32_t*)pB);
    }
    // 3) CSA popcount GEMM, 2 CTAs/SM
    cudaFuncSetAttribute(popc_gemm, cudaFuncAttributeMaxDynamicSharedMemorySize, GEMM_SMEM);
    dim3 grid(NUNITS / 128, BDIM / 128);       // (16, 64)
    popc_gemm<<<grid, 256, GEMM_SMEM>>>((const uint32_t*)pA, (const uint32_t*)pB, bias, out);
}